// round 7
// baseline (speedup 1.0000x reference)
#include <cuda_runtime.h>
#include <cstdint>

#define N_NODES 100000
#define N_EDGES 1000000
#define F 64
#define G 128

#define TN 48
#define NPT 12
#define WPAD 68
#define GEMM_BLOCKS 592
#define EDGE_TPE 4
#define EDGE_BLOCKS ((N_EDGES * EDGE_TPE + 255) / 256)   // 15625

// ---------------- scratch (static device globals; no allocation) ----------
__device__ __align__(16) float d_AGG[(size_t)N_NODES * F]; // sum_e w * x[src] (x-space)
__device__ __align__(16) float d_H [(size_t)N_NODES * F];  // x @ w1root.T + b1
__device__ float d_a [N_NODES];      // relu(h1) . v_rel
__device__ float d_S [N_NODES];      // root scalar of layer2 (+c2), then += edges
__device__ float d_vrel[F];
__device__ float d_vroot[F];
__device__ float d_c2;
__device__ float d_gsum[G];
__device__ float d_gcnt[G];

// ---------------- zero the x-space aggregation buffer ---------------------
__global__ __launch_bounds__(256)
void k_zero() {
    size_t i = (size_t)blockIdx.x * 256 + threadIdx.x;   // float4 index
    float4* p = reinterpret_cast<float4*>(d_AGG);
    if (i < (size_t)N_NODES * F / 4)
        p[i] = make_float4(0.f, 0.f, 0.f, 0.f);
}

// ---------------- init: collapse layer2+readout weights, zero pools -------
__global__ void k_init(const float* __restrict__ w2rel,
                       const float* __restrict__ w2root,
                       const float* __restrict__ b2,
                       const float* __restrict__ wlin) {
    int t = threadIdx.x;  // 128 threads
    if (t < G) { d_gsum[t] = 0.f; d_gcnt[t] = 0.f; }
    if (t < F) {
        float vr = 0.f, vo = 0.f;
        #pragma unroll 8
        for (int h = 0; h < F; h++) {
            float wl = wlin[h];
            vr += wl * w2rel[h * F + t];
            vo += wl * w2root[h * F + t];
        }
        d_vrel[t] = vr; d_vroot[t] = vo;
    }
    if (t == 0) {
        float c = 0.f;
        for (int h = 0; h < F; h++) c += wlin[h] * b2[h];
        d_c2 = c;
    }
}

// ---- phase 1: [blocks < GEMM_BLOCKS]  d_H = x @ w1root.T + b1  (persistent)
//               [blocks >= GEMM_BLOCKS] d_AGG[dst] += w_e * x[src] (scatter)
// Both sides read only kernel inputs -> they run concurrently in one launch.
__global__ __launch_bounds__(256)
void k_phase1(const float* __restrict__ x, const float* __restrict__ w1root,
              const float* __restrict__ b1,
              const int* __restrict__ ei, const float* __restrict__ ew) {
    __shared__ float sW[F * WPAD];
    __shared__ float sX[TN * F];

    if (blockIdx.x >= GEMM_BLOCKS) {
        // ------- edge scatter branch: 4 threads per edge, red.v4 ----------
        int gid = (blockIdx.x - GEMM_BLOCKS) * 256 + threadIdx.x;
        int e = gid >> 2;
        int r = gid & 3;
        if (e >= N_EDGES) return;
        int src = ei[e];
        int dst = ei[N_EDGES + e];
        float w = ew[e];
        const float4* xs = reinterpret_cast<const float4*>(x) + (size_t)src * 16;
        float4*       ag = reinterpret_cast<float4*>(d_AGG)   + (size_t)dst * 16;
        #pragma unroll
        for (int c = 0; c < 4; c++) {
            float4 v = xs[r + c * 4];
            v.x *= w; v.y *= w; v.z *= w; v.w *= w;
            unsigned long long gp = __cvta_generic_to_global(ag + r + c * 4);
            asm volatile("red.global.add.v4.f32 [%0], {%1,%2,%3,%4};"
                         :: "l"(gp), "f"(v.x), "f"(v.y), "f"(v.z), "f"(v.w)
                         : "memory");
        }
        return;
    }

    // ------- root GEMM branch ---------------------------------------------
    int tid = threadIdx.x;
    for (int i = tid; i < F * F; i += 256)
        sW[(i >> 6) * WPAD + (i & 63)] = w1root[i];

    int oc = tid & 63;
    int ns = tid >> 6;
    float bb = b1[oc];
    float4* xs4 = reinterpret_cast<float4*>(sX);
    const int ntiles = (N_NODES + TN - 1) / TN;

    for (int tile = blockIdx.x; tile < ntiles; tile += GEMM_BLOCKS) {
        int nbase  = tile * TN;
        int nvalid = min(TN, N_NODES - nbase);
        __syncthreads();
        const float4* xg = reinterpret_cast<const float4*>(x + (size_t)nbase * F);
        #pragma unroll
        for (int i = 0; i < 3; i++) {
            int idx  = tid + i * 256;
            int node = idx >> 4;
            float4 v = make_float4(0.f, 0.f, 0.f, 0.f);
            if (node < nvalid) v = xg[idx];
            xs4[idx] = v;
        }
        __syncthreads();

        float acc[NPT];
        #pragma unroll
        for (int i = 0; i < NPT; i++) acc[i] = 0.f;

        #pragma unroll
        for (int k4 = 0; k4 < 16; k4++) {
            float4 wv = *reinterpret_cast<const float4*>(&sW[oc * WPAD + k4 * 4]);
            #pragma unroll
            for (int i = 0; i < NPT; i++) {
                float4 xv = xs4[(ns + i * 4) * 16 + k4];
                acc[i] += xv.x * wv.x + xv.y * wv.y + xv.z * wv.z + xv.w * wv.w;
            }
        }
        #pragma unroll
        for (int i = 0; i < NPT; i++) {
            int node = ns + i * 4;
            if (node < nvalid)
                d_H[(size_t)(nbase + node) * F + oc] = acc[i] + bb;
        }
    }
}

// ---- phase 2: h1 = relu(d_AGG @ w1rel.T + d_H); d_a = h1.vrel; d_S = h1.vroot + c2
__global__ __launch_bounds__(256)
void k_phase2(const float* __restrict__ w1rel) {
    __shared__ float sW[F * WPAD];
    __shared__ float sX[TN * F];
    __shared__ float sPa[TN][2];
    __shared__ float sPs[TN][2];

    int tid = threadIdx.x;
    for (int i = tid; i < F * F; i += 256)
        sW[(i >> 6) * WPAD + (i & 63)] = w1rel[i];

    int oc   = tid & 63;
    int ns   = tid >> 6;
    int half = (tid >> 5) & 1;
    int lane = tid & 31;
    float vrel  = d_vrel[oc];
    float vroot = d_vroot[oc];
    float c2    = d_c2;
    float4* xs4 = reinterpret_cast<float4*>(sX);
    const int ntiles = (N_NODES + TN - 1) / TN;

    for (int tile = blockIdx.x; tile < ntiles; tile += gridDim.x) {
        int nbase  = tile * TN;
        int nvalid = min(TN, N_NODES - nbase);
        __syncthreads();
        const float4* xg = reinterpret_cast<const float4*>(d_AGG + (size_t)nbase * F);
        #pragma unroll
        for (int i = 0; i < 3; i++) {
            int idx  = tid + i * 256;
            int node = idx >> 4;
            float4 v = make_float4(0.f, 0.f, 0.f, 0.f);
            if (node < nvalid) v = xg[idx];
            xs4[idx] = v;
        }
        __syncthreads();

        float acc[NPT];
        #pragma unroll
        for (int i = 0; i < NPT; i++) acc[i] = 0.f;

        #pragma unroll
        for (int k4 = 0; k4 < 16; k4++) {
            float4 wv = *reinterpret_cast<const float4*>(&sW[oc * WPAD + k4 * 4]);
            #pragma unroll
            for (int i = 0; i < NPT; i++) {
                float4 xv = xs4[(ns + i * 4) * 16 + k4];
                acc[i] += xv.x * wv.x + xv.y * wv.y + xv.z * wv.z + xv.w * wv.w;
            }
        }

        // fused epilogue: + root part, relu, dual dot with warp reduction
        #pragma unroll
        for (int i = 0; i < NPT; i++) {
            int node = ns + i * 4;
            float hr = (node < nvalid)
                     ? d_H[(size_t)(nbase + node) * F + oc] : 0.f;
            float h  = fmaxf(acc[i] + hr, 0.f);
            float pa = h * vrel;
            float ps = h * vroot;
            #pragma unroll
            for (int o = 16; o; o >>= 1) {
                pa += __shfl_xor_sync(0xffffffffu, pa, o);
                ps += __shfl_xor_sync(0xffffffffu, ps, o);
            }
            if (lane == 0) { sPa[node][half] = pa; sPs[node][half] = ps; }
        }
        __syncthreads();
        if (tid < nvalid) {
            d_a[nbase + tid] = sPa[tid][0] + sPa[tid][1];
            d_S[nbase + tid] = sPs[tid][0] + sPs[tid][1] + c2;
        }
    }
}

// ---------------- layer-2 scalar edge pass --------------------------------
__global__ __launch_bounds__(256)
void k_edge2(const int* __restrict__ ei, const float* __restrict__ ew) {
    int e = blockIdx.x * blockDim.x + threadIdx.x;
    if (e >= N_EDGES) return;
    int src = ei[e];
    int dst = ei[N_EDGES + e];
    atomicAdd(&d_S[dst], ew[e] * d_a[src]);
}

// ---------------- mean-pool bins ------------------------------------------
__global__ __launch_bounds__(256)
void k_pool(const int* __restrict__ batch) {
    __shared__ float sb[G];
    __shared__ float sc[G];
    int tid = threadIdx.x;
    if (tid < G) { sb[tid] = 0.f; sc[tid] = 0.f; }
    __syncthreads();
    for (int n = blockIdx.x * blockDim.x + tid; n < N_NODES;
         n += gridDim.x * blockDim.x) {
        int g = batch[n];
        atomicAdd(&sb[g], d_S[n]);
        atomicAdd(&sc[g], 1.0f);
    }
    __syncthreads();
    if (tid < G && (sb[tid] != 0.f || sc[tid] != 0.f)) {
        atomicAdd(&d_gsum[tid], sb[tid]);
        atomicAdd(&d_gcnt[tid], sc[tid]);
    }
}

// ---------------- final ----------------------------------------------------
__global__ void k_final(const float* __restrict__ blin, float* __restrict__ out) {
    int g = threadIdx.x;
    if (g < G) out[g] = d_gsum[g] / fmaxf(d_gcnt[g], 1.0f) + blin[0];
}

// ---------------- launch ---------------------------------------------------
extern "C" void kernel_launch(void* const* d_in, const int* in_sizes, int n_in,
                              void* d_out, int out_size) {
    const float* x     = (const float*)d_in[0];
    const int*   ei    = (const int*)d_in[1];      // int32 (JAX x64 disabled)
    const float* ew    = (const float*)d_in[2];
    const int*   batch = (const int*)d_in[3];
    const float* w1rel = (const float*)d_in[4];
    const float* b1rel = (const float*)d_in[5];
    const float* w1rt  = (const float*)d_in[6];
    const float* w2rel = (const float*)d_in[7];
    const float* b2rel = (const float*)d_in[8];
    const float* w2rt  = (const float*)d_in[9];
    const float* wlin  = (const float*)d_in[10];
    const float* blin  = (const float*)d_in[11];
    float* out = (float*)d_out;

    k_zero<<<(N_NODES * F / 4 + 255) / 256, 256>>>();
    k_init<<<1, 128>>>(w2rel, w2rt, b2rel, wlin);
    k_phase1<<<GEMM_BLOCKS + EDGE_BLOCKS, 256>>>(x, w1rt, b1rel, ei, ew);
    k_phase2<<<GEMM_BLOCKS, 256>>>(w1rel);
    k_edge2<<<(N_EDGES + 255) / 256, 256>>>(ei, ew);
    k_pool<<<128, 256>>>(batch);
    k_final<<<1, 128>>>(blin, out);
}

// round 8
// speedup vs baseline: 1.3035x; 1.3035x over previous
#include <cuda_runtime.h>
#include <cstdint>

#define N_NODES 100000
#define N_EDGES 1000000
#define F 64
#define G 128
#define SCANB 1024
#define NSCAN ((N_NODES + SCANB - 1) / SCANB)   // 98

// ---------------- scratch (static device globals; no allocation) ----------
__device__ __align__(16) float d_XR[(size_t)N_NODES * F];  // x @ w1_rel.T
__device__ __align__(16) float d_H [(size_t)N_NODES * F];  // x @ w1_root.T + b1
__device__ float d_a [N_NODES];
__device__ float d_S [N_NODES];
__device__ float d_vrel[F];
__device__ float d_vroot[F];
__device__ float d_c2;
__device__ float d_gsum[G];
__device__ float d_gcnt[G];
// CSR by dst
__device__ int   d_deg[N_NODES];
__device__ int   d_off[N_NODES];
__device__ int   d_cursor[N_NODES];
__device__ int   d_part[128];
__device__ __align__(8) int2 d_ep[N_EDGES];   // {src, __float_as_int(w)}

// ---------------- init ----------------------------------------------------
__global__ void k_init(const float* __restrict__ w2rel,
                       const float* __restrict__ w2root,
                       const float* __restrict__ b2,
                       const float* __restrict__ wlin) {
    int t = threadIdx.x;  // 128
    if (t < G) { d_gsum[t] = 0.f; d_gcnt[t] = 0.f; }
    if (t < F) {
        float vr = 0.f, vo = 0.f;
        #pragma unroll 8
        for (int h = 0; h < F; h++) {
            float wl = wlin[h];
            vr += wl * w2rel[h * F + t];
            vo += wl * w2root[h * F + t];
        }
        d_vrel[t] = vr; d_vroot[t] = vo;
    }
    if (t == 0) {
        float c = 0.f;
        for (int h = 0; h < F; h++) c += wlin[h] * b2[h];
        d_c2 = c;
    }
}

__global__ void k_zero_deg() {
    int n = blockIdx.x * blockDim.x + threadIdx.x;
    if (n < N_NODES) d_deg[n] = 0;
}

// ---- dual GEMM, register-blocked outer product, packed f32x2 FMA ---------
// [XR | H] = X[128-tile, 64] @ Wt[64, 128]   (Wt = concat(w1rel; w1root).T)
#define XPAD 68
#define WTPAD 132
#define SM_X_OFF 0
#define SM_WT_OFF (128 * XPAD)                 // floats
#define SMEM_FLOATS (128 * XPAD + 64 * WTPAD)  // 17152 floats = 68608 B

__global__ __launch_bounds__(256, 2)
void k_gemm(const float* __restrict__ x, const float* __restrict__ w1rel,
            const float* __restrict__ w1root, const float* __restrict__ b1) {
    extern __shared__ float sm[];
    float* sX  = sm + SM_X_OFF;    // [128][XPAD]
    float* sWt = sm + SM_WT_OFF;   // [64][WTPAD]

    int tid = threadIdx.x;
    // load + transpose weights once: sWt[k][o] = W[o][k]
    for (int idx = tid; idx < 128 * 64; idx += 256) {
        int o = idx >> 6, k = idx & 63;
        float v = (o < 64) ? w1rel[o * 64 + k] : w1root[(o - 64) * 64 + k];
        sWt[k * WTPAD + o] = v;
    }

    int tr = tid >> 4;            // 0..15 -> node group of 8
    int tc = tid & 15;            // 0..15 -> out group of 8
    int n0 = tr * 8;
    int o0 = tc * 8;
    // bias (H half only)
    float bb[8];
    #pragma unroll
    for (int q = 0; q < 8; q++) bb[q] = (tc >= 8) ? b1[o0 - 64 + q] : 0.f;

    const int ntiles = (N_NODES + 127) / 128;   // 782
    for (int tile = blockIdx.x; tile < ntiles; tile += gridDim.x) {
        int nbase  = tile * 128;
        int nvalid = min(128, N_NODES - nbase);
        __syncthreads();
        // load X tile (float4 granularity)
        const float4* xg = reinterpret_cast<const float4*>(x + (size_t)nbase * F);
        #pragma unroll
        for (int i = 0; i < 8; i++) {
            int idx = tid + i * 256;           // 0..2047
            int row = idx >> 4, c4 = idx & 15;
            float4 v = make_float4(0.f, 0.f, 0.f, 0.f);
            if (row < nvalid) v = xg[idx];
            *reinterpret_cast<float4*>(&sX[row * XPAD + c4 * 4]) = v;
        }
        __syncthreads();

        unsigned long long acc[8][4];
        #pragma unroll
        for (int n = 0; n < 8; n++)
            #pragma unroll
            for (int p = 0; p < 4; p++) acc[n][p] = 0ull;

        #pragma unroll 4
        for (int kk = 0; kk < 64; kk += 4) {
            unsigned long long b[4][4];
            #pragma unroll
            for (int j = 0; j < 4; j++) {
                ulonglong2 t0 = *reinterpret_cast<const ulonglong2*>(&sWt[(kk + j) * WTPAD + o0]);
                ulonglong2 t1 = *reinterpret_cast<const ulonglong2*>(&sWt[(kk + j) * WTPAD + o0 + 4]);
                b[j][0] = t0.x; b[j][1] = t0.y; b[j][2] = t1.x; b[j][3] = t1.y;
            }
            #pragma unroll
            for (int n = 0; n < 8; n++) {
                float4 av = *reinterpret_cast<const float4*>(&sX[(n0 + n) * XPAD + kk]);
                float as[4] = {av.x, av.y, av.z, av.w};
                #pragma unroll
                for (int j = 0; j < 4; j++) {
                    unsigned long long a2;
                    asm("mov.b64 %0, {%1, %1};" : "=l"(a2) : "f"(as[j]));
                    #pragma unroll
                    for (int p = 0; p < 4; p++)
                        asm("fma.rn.f32x2 %0, %1, %2, %3;"
                            : "=l"(acc[n][p])
                            : "l"(a2), "l"(b[j][p]), "l"(acc[n][p]));
                }
            }
        }

        // store: tc<8 -> XR, tc>=8 -> H (+bias)
        #pragma unroll
        for (int n = 0; n < 8; n++) {
            int node = n0 + n;
            if (node >= nvalid) break;
            float o_[8];
            #pragma unroll
            for (int p = 0; p < 4; p++) {
                o_[2*p]   = __uint_as_float((unsigned)(acc[n][p] & 0xffffffffu));
                o_[2*p+1] = __uint_as_float((unsigned)(acc[n][p] >> 32));
            }
            size_t gbase = (size_t)(nbase + node) * F;
            if (tc < 8) {
                *reinterpret_cast<float4*>(&d_XR[gbase + o0]) =
                    make_float4(o_[0], o_[1], o_[2], o_[3]);
                *reinterpret_cast<float4*>(&d_XR[gbase + o0 + 4]) =
                    make_float4(o_[4], o_[5], o_[6], o_[7]);
            } else {
                *reinterpret_cast<float4*>(&d_H[gbase + o0 - 64]) =
                    make_float4(o_[0] + bb[0], o_[1] + bb[1], o_[2] + bb[2], o_[3] + bb[3]);
                *reinterpret_cast<float4*>(&d_H[gbase + o0 - 60]) =
                    make_float4(o_[4] + bb[4], o_[5] + bb[5], o_[6] + bb[6], o_[7] + bb[7]);
            }
        }
    }
}

// ---------------- CSR build ------------------------------------------------
__global__ __launch_bounds__(256)
void k_deg(const int* __restrict__ ei) {
    int e = blockIdx.x * blockDim.x + threadIdx.x;
    if (e >= N_EDGES) return;
    atomicAdd(&d_deg[ei[N_EDGES + e]], 1);
}

__global__ void k_scanA() {
    __shared__ int s[SCANB];
    int tid = threadIdx.x;
    int n = blockIdx.x * SCANB + tid;
    s[tid] = (n < N_NODES) ? d_deg[n] : 0;
    __syncthreads();
    for (int o = SCANB / 2; o; o >>= 1) {
        if (tid < o) s[tid] += s[tid + o];
        __syncthreads();
    }
    if (tid == 0) d_part[blockIdx.x] = s[0];
}

__global__ void k_scanB() {
    if (threadIdx.x == 0) {
        int acc = 0;
        for (int i = 0; i < NSCAN; i++) { int t = d_part[i]; d_part[i] = acc; acc += t; }
    }
}

__global__ void k_scanC() {
    __shared__ int s[SCANB];
    int tid = threadIdx.x;
    int n = blockIdx.x * SCANB + tid;
    int v = (n < N_NODES) ? d_deg[n] : 0;
    s[tid] = v;
    __syncthreads();
    for (int o = 1; o < SCANB; o <<= 1) {
        int t = (tid >= o) ? s[tid - o] : 0;
        __syncthreads();
        s[tid] += t;
        __syncthreads();
    }
    if (n < N_NODES) {
        int off = d_part[blockIdx.x] + s[tid] - v;
        d_off[n] = off;
        d_cursor[n] = off;
    }
}

__global__ __launch_bounds__(256)
void k_fill(const int* __restrict__ ei, const float* __restrict__ ew) {
    int e = blockIdx.x * blockDim.x + threadIdx.x;
    if (e >= N_EDGES) return;
    int src = ei[e];
    int dst = ei[N_EDGES + e];
    int slot = atomicAdd(&d_cursor[dst], 1);
    d_ep[slot] = make_int2(src, __float_as_int(ew[e]));
}

// ---- aggr: warp/node, 4-edge unrolled gather; fused relu + dual dot ------
__global__ __launch_bounds__(256)
void k_aggr() {
    int node = (blockIdx.x * blockDim.x + threadIdx.x) >> 5;
    int l    = threadIdx.x & 31;
    if (node >= N_NODES) return;
    int beg = d_off[node];
    int end = beg + d_deg[node];
    float a0 = 0.f, a1 = 0.f;
    int j = beg;
    for (; j + 4 <= end; j += 4) {
        int2 e0 = d_ep[j],     e1 = d_ep[j + 1];
        int2 e2 = d_ep[j + 2], e3 = d_ep[j + 3];
        const float* p0 = d_XR + (size_t)e0.x * F;
        const float* p1 = d_XR + (size_t)e1.x * F;
        const float* p2 = d_XR + (size_t)e2.x * F;
        const float* p3 = d_XR + (size_t)e3.x * F;
        float q00 = p0[l], q01 = p0[l + 32];
        float q10 = p1[l], q11 = p1[l + 32];
        float q20 = p2[l], q21 = p2[l + 32];
        float q30 = p3[l], q31 = p3[l + 32];
        float w0 = __int_as_float(e0.y), w1 = __int_as_float(e1.y);
        float w2 = __int_as_float(e2.y), w3 = __int_as_float(e3.y);
        a0 = fmaf(w0, q00, a0); a1 = fmaf(w0, q01, a1);
        a0 = fmaf(w1, q10, a0); a1 = fmaf(w1, q11, a1);
        a0 = fmaf(w2, q20, a0); a1 = fmaf(w2, q21, a1);
        a0 = fmaf(w3, q30, a0); a1 = fmaf(w3, q31, a1);
    }
    for (; j < end; j++) {
        int2 e = d_ep[j];
        const float* p = d_XR + (size_t)e.x * F;
        float w = __int_as_float(e.y);
        a0 = fmaf(w, p[l],      a0);
        a1 = fmaf(w, p[l + 32], a1);
    }
    const float* h = d_H + (size_t)node * F;
    float h0 = fmaxf(h[l]      + a0, 0.f);
    float h1 = fmaxf(h[l + 32] + a1, 0.f);
    float pa = h0 * d_vrel[l]  + h1 * d_vrel[l + 32];
    float ps = h0 * d_vroot[l] + h1 * d_vroot[l + 32];
    #pragma unroll
    for (int o = 16; o; o >>= 1) {
        pa += __shfl_xor_sync(0xffffffffu, pa, o);
        ps += __shfl_xor_sync(0xffffffffu, ps, o);
    }
    if (l == 0) { d_a[node] = pa; d_S[node] = ps + d_c2; }
}

// ---- layer2 scalar aggregation (CSR gather, unrolled) + pool bins --------
__global__ __launch_bounds__(256)
void k_scalar_pool(const int* __restrict__ batch) {
    __shared__ float sb[G];
    __shared__ float sc[G];
    int tid = threadIdx.x;
    if (tid < G) { sb[tid] = 0.f; sc[tid] = 0.f; }
    __syncthreads();
    int n = blockIdx.x * blockDim.x + tid;
    if (n < N_NODES) {
        int beg = d_off[n];
        int end = beg + d_deg[n];
        float s = 0.f;
        int j = beg;
        for (; j + 4 <= end; j += 4) {
            int2 e0 = d_ep[j],     e1 = d_ep[j + 1];
            int2 e2 = d_ep[j + 2], e3 = d_ep[j + 3];
            float v0 = d_a[e0.x], v1 = d_a[e1.x];
            float v2 = d_a[e2.x], v3 = d_a[e3.x];
            s = fmaf(__int_as_float(e0.y), v0, s);
            s = fmaf(__int_as_float(e1.y), v1, s);
            s = fmaf(__int_as_float(e2.y), v2, s);
            s = fmaf(__int_as_float(e3.y), v3, s);
        }
        for (; j < end; j++) {
            int2 e = d_ep[j];
            s = fmaf(__int_as_float(e.y), d_a[e.x], s);
        }
        float S = d_S[n] + s;
        int b = batch[n];
        atomicAdd(&sb[b], S);
        atomicAdd(&sc[b], 1.0f);
    }
    __syncthreads();
    if (tid < G && (sb[tid] != 0.f || sc[tid] != 0.f)) {
        atomicAdd(&d_gsum[tid], sb[tid]);
        atomicAdd(&d_gcnt[tid], sc[tid]);
    }
}

// ---------------- final ----------------------------------------------------
__global__ void k_final(const float* __restrict__ blin, float* __restrict__ out) {
    int g = threadIdx.x;
    if (g < G) out[g] = d_gsum[g] / fmaxf(d_gcnt[g], 1.0f) + blin[0];
}

// ---------------- launch ---------------------------------------------------
extern "C" void kernel_launch(void* const* d_in, const int* in_sizes, int n_in,
                              void* d_out, int out_size) {
    const float* x     = (const float*)d_in[0];
    const int*   ei    = (const int*)d_in[1];      // int32 (JAX x64 disabled)
    const float* ew    = (const float*)d_in[2];
    const int*   batch = (const int*)d_in[3];
    const float* w1rel = (const float*)d_in[4];
    const float* b1rel = (const float*)d_in[5];
    const float* w1rt  = (const float*)d_in[6];
    const float* w2rel = (const float*)d_in[7];
    const float* b2rel = (const float*)d_in[8];
    const float* w2rt  = (const float*)d_in[9];
    const float* wlin  = (const float*)d_in[10];
    const float* blin  = (const float*)d_in[11];
    float* out = (float*)d_out;

    cudaFuncSetAttribute(k_gemm, cudaFuncAttributeMaxDynamicSharedMemorySize,
                         SMEM_FLOATS * 4);

    k_init<<<1, 128>>>(w2rel, w2rt, b2rel, wlin);
    k_zero_deg<<<NSCAN, SCANB>>>();
    k_deg<<<(N_EDGES + 255) / 256, 256>>>(ei);
    k_gemm<<<296, 256, SMEM_FLOATS * 4>>>(x, w1rel, w1rt, b1rel);
    k_scanA<<<NSCAN, SCANB>>>();
    k_scanB<<<1, 32>>>();
    k_scanC<<<NSCAN, SCANB>>>();
    k_fill<<<(N_EDGES + 255) / 256, 256>>>(ei, ew);
    k_aggr<<<(N_NODES * 32 + 255) / 256, 256>>>();
    k_scalar_pool<<<(N_NODES + 255) / 256, 256>>>(batch);
    k_final<<<1, 128>>>(blin, out);
}

// round 9
// speedup vs baseline: 1.3801x; 1.0588x over previous
#include <cuda_runtime.h>
#include <cstdint>

#define N_NODES 100000
#define N_EDGES 1000000
#define F 64
#define G 128
#define SCANB 1024
#define NSCAN ((N_NODES + SCANB - 1) / SCANB)   // 98

// ---------------- scratch (static device globals; no allocation) ----------
__device__ __align__(16) float d_XR[(size_t)N_NODES * F];  // x @ w1_rel.T
__device__ __align__(16) float d_H [(size_t)N_NODES * F];  // x @ w1_root.T + b1
__device__ float d_a [N_NODES];
__device__ float d_S [N_NODES];
__device__ __align__(8) float d_vrel[F];
__device__ __align__(8) float d_vroot[F];
__device__ float d_c2;
__device__ float d_gsum[G];
__device__ float d_gcnt[G];
// CSR by dst
__device__ int   d_deg[N_NODES];
__device__ int   d_off[N_NODES];
__device__ int   d_cursor[N_NODES];
__device__ int   d_part[128];
__device__ __align__(8) int2 d_ep[N_EDGES];   // {src, __float_as_int(w)}

// ------- init (block 0) + zero degree histogram (all blocks) --------------
__global__ __launch_bounds__(256)
void k_init_zero(const float* __restrict__ w2rel,
                 const float* __restrict__ w2root,
                 const float* __restrict__ b2,
                 const float* __restrict__ wlin) {
    int tid = threadIdx.x;
    if (blockIdx.x == 0) {
        if (tid < G) { d_gsum[tid] = 0.f; d_gcnt[tid] = 0.f; }
        if (tid < F) {
            float vr = 0.f, vo = 0.f;
            #pragma unroll 8
            for (int h = 0; h < F; h++) {
                float wl = wlin[h];
                vr += wl * w2rel[h * F + tid];
                vo += wl * w2root[h * F + tid];
            }
            d_vrel[tid] = vr; d_vroot[tid] = vo;
        }
        if (tid == 0) {
            float c = 0.f;
            for (int h = 0; h < F; h++) c += wlin[h] * b2[h];
            d_c2 = c;
        }
    }
    int n = blockIdx.x * 256 + tid;
    if (n < N_NODES) d_deg[n] = 0;
}

// ---- dual GEMM (f32x2 outer product) + inlined degree count prologue -----
// [XR | H] = X[128-tile, 64] @ Wt[64, 128]   (Wt = concat(w1rel; w1root).T)
#define XPAD 68
#define WTPAD 132
#define SM_X_OFF 0
#define SM_WT_OFF (128 * XPAD)                 // floats
#define SMEM_FLOATS (128 * XPAD + 64 * WTPAD)  // 17152 floats = 68608 B
#define GEMM_GRID 296

__global__ __launch_bounds__(256, 2)
void k_gemm(const float* __restrict__ x, const float* __restrict__ w1rel,
            const float* __restrict__ w1root, const float* __restrict__ b1,
            const int* __restrict__ ei) {
    extern __shared__ float sm[];
    float* sX  = sm + SM_X_OFF;    // [128][XPAD]
    float* sWt = sm + SM_WT_OFF;   // [64][WTPAD]

    int tid = threadIdx.x;

    // --- degree-count prologue: fire-and-forget RED atomics (hidden work) --
    {
        int gtid = blockIdx.x * 256 + tid;
        for (int e = gtid; e < N_EDGES; e += GEMM_GRID * 256)
            atomicAdd(&d_deg[ei[N_EDGES + e]], 1);
    }

    // load + transpose weights once: sWt[k][o] = W[o][k]
    for (int idx = tid; idx < 128 * 64; idx += 256) {
        int o = idx >> 6, k = idx & 63;
        float v = (o < 64) ? w1rel[o * 64 + k] : w1root[(o - 64) * 64 + k];
        sWt[k * WTPAD + o] = v;
    }

    int tr = tid >> 4;            // 0..15 -> node group of 8
    int tc = tid & 15;            // 0..15 -> out group of 8
    int n0 = tr * 8;
    int o0 = tc * 8;
    float bb[8];
    #pragma unroll
    for (int q = 0; q < 8; q++) bb[q] = (tc >= 8) ? b1[o0 - 64 + q] : 0.f;

    const int ntiles = (N_NODES + 127) / 128;   // 782
    for (int tile = blockIdx.x; tile < ntiles; tile += gridDim.x) {
        int nbase  = tile * 128;
        int nvalid = min(128, N_NODES - nbase);
        __syncthreads();
        const float4* xg = reinterpret_cast<const float4*>(x + (size_t)nbase * F);
        #pragma unroll
        for (int i = 0; i < 8; i++) {
            int idx = tid + i * 256;           // 0..2047
            int row = idx >> 4, c4 = idx & 15;
            float4 v = make_float4(0.f, 0.f, 0.f, 0.f);
            if (row < nvalid) v = xg[idx];
            *reinterpret_cast<float4*>(&sX[row * XPAD + c4 * 4]) = v;
        }
        __syncthreads();

        unsigned long long acc[8][4];
        #pragma unroll
        for (int n = 0; n < 8; n++)
            #pragma unroll
            for (int p = 0; p < 4; p++) acc[n][p] = 0ull;

        #pragma unroll 4
        for (int kk = 0; kk < 64; kk += 4) {
            unsigned long long b[4][4];
            #pragma unroll
            for (int j = 0; j < 4; j++) {
                ulonglong2 t0 = *reinterpret_cast<const ulonglong2*>(&sWt[(kk + j) * WTPAD + o0]);
                ulonglong2 t1 = *reinterpret_cast<const ulonglong2*>(&sWt[(kk + j) * WTPAD + o0 + 4]);
                b[j][0] = t0.x; b[j][1] = t0.y; b[j][2] = t1.x; b[j][3] = t1.y;
            }
            #pragma unroll
            for (int n = 0; n < 8; n++) {
                float4 av = *reinterpret_cast<const float4*>(&sX[(n0 + n) * XPAD + kk]);
                float as[4] = {av.x, av.y, av.z, av.w};
                #pragma unroll
                for (int j = 0; j < 4; j++) {
                    unsigned long long a2;
                    asm("mov.b64 %0, {%1, %1};" : "=l"(a2) : "f"(as[j]));
                    #pragma unroll
                    for (int p = 0; p < 4; p++)
                        asm("fma.rn.f32x2 %0, %1, %2, %3;"
                            : "=l"(acc[n][p])
                            : "l"(a2), "l"(b[j][p]), "l"(acc[n][p]));
                }
            }
        }

        #pragma unroll
        for (int n = 0; n < 8; n++) {
            int node = n0 + n;
            if (node >= nvalid) break;
            float o_[8];
            #pragma unroll
            for (int p = 0; p < 4; p++) {
                o_[2*p]   = __uint_as_float((unsigned)(acc[n][p] & 0xffffffffu));
                o_[2*p+1] = __uint_as_float((unsigned)(acc[n][p] >> 32));
            }
            size_t gbase = (size_t)(nbase + node) * F;
            if (tc < 8) {
                *reinterpret_cast<float4*>(&d_XR[gbase + o0]) =
                    make_float4(o_[0], o_[1], o_[2], o_[3]);
                *reinterpret_cast<float4*>(&d_XR[gbase + o0 + 4]) =
                    make_float4(o_[4], o_[5], o_[6], o_[7]);
            } else {
                *reinterpret_cast<float4*>(&d_H[gbase + o0 - 64]) =
                    make_float4(o_[0] + bb[0], o_[1] + bb[1], o_[2] + bb[2], o_[3] + bb[3]);
                *reinterpret_cast<float4*>(&d_H[gbase + o0 - 60]) =
                    make_float4(o_[4] + bb[4], o_[5] + bb[5], o_[6] + bb[6], o_[7] + bb[7]);
            }
        }
    }
}

// ---------------- CSR scans -----------------------------------------------
__global__ void k_scanA() {
    __shared__ int s[SCANB];
    int tid = threadIdx.x;
    int n = blockIdx.x * SCANB + tid;
    s[tid] = (n < N_NODES) ? d_deg[n] : 0;
    __syncthreads();
    for (int o = SCANB / 2; o; o >>= 1) {
        if (tid < o) s[tid] += s[tid + o];
        __syncthreads();
    }
    if (tid == 0) d_part[blockIdx.x] = s[0];
}

__global__ void k_scanB() {
    if (threadIdx.x == 0) {
        int acc = 0;
        for (int i = 0; i < NSCAN; i++) { int t = d_part[i]; d_part[i] = acc; acc += t; }
    }
}

__global__ void k_scanC() {
    __shared__ int s[SCANB];
    int tid = threadIdx.x;
    int n = blockIdx.x * SCANB + tid;
    int v = (n < N_NODES) ? d_deg[n] : 0;
    s[tid] = v;
    __syncthreads();
    for (int o = 1; o < SCANB; o <<= 1) {
        int t = (tid >= o) ? s[tid - o] : 0;
        __syncthreads();
        s[tid] += t;
        __syncthreads();
    }
    if (n < N_NODES) {
        int off = d_part[blockIdx.x] + s[tid] - v;
        d_off[n] = off;
        d_cursor[n] = off;
    }
}

__global__ __launch_bounds__(256)
void k_fill(const int* __restrict__ ei, const float* __restrict__ ew) {
    int e = blockIdx.x * blockDim.x + threadIdx.x;
    if (e >= N_EDGES) return;
    int src = ei[e];
    int dst = ei[N_EDGES + e];
    int slot = atomicAdd(&d_cursor[dst], 1);
    d_ep[slot] = make_int2(src, __float_as_int(ew[e]));
}

// ---- aggr: warp/node, float2 lanes (full 256B row per LDG.64 warp-wide), --
// ---- 8-edge unrolled gather; fused relu + dual dot ------------------------
__global__ __launch_bounds__(256)
void k_aggr() {
    int node = (blockIdx.x * blockDim.x + threadIdx.x) >> 5;
    int l    = threadIdx.x & 31;
    if (node >= N_NODES) return;
    int beg = d_off[node];
    int end = beg + d_deg[node];
    float a0 = 0.f, a1 = 0.f;
    const float2* XR2 = reinterpret_cast<const float2*>(d_XR);
    int j = beg;
    for (; j + 8 <= end; j += 8) {
        int2 e[8];
        #pragma unroll
        for (int q = 0; q < 8; q++) e[q] = d_ep[j + q];
        float2 v[8];
        #pragma unroll
        for (int q = 0; q < 8; q++) v[q] = XR2[(size_t)e[q].x * 32 + l];
        #pragma unroll
        for (int q = 0; q < 8; q++) {
            float w = __int_as_float(e[q].y);
            a0 = fmaf(w, v[q].x, a0);
            a1 = fmaf(w, v[q].y, a1);
        }
    }
    for (; j < end; j++) {
        int2 e = d_ep[j];
        float2 v = XR2[(size_t)e.x * 32 + l];
        float w = __int_as_float(e.y);
        a0 = fmaf(w, v.x, a0);
        a1 = fmaf(w, v.y, a1);
    }
    float2 hh = reinterpret_cast<const float2*>(d_H)[(size_t)node * 32 + l];
    float h0 = fmaxf(hh.x + a0, 0.f);
    float h1 = fmaxf(hh.y + a1, 0.f);
    float2 vr = reinterpret_cast<const float2*>(d_vrel)[l];
    float2 vo = reinterpret_cast<const float2*>(d_vroot)[l];
    float pa = h0 * vr.x + h1 * vr.y;
    float ps = h0 * vo.x + h1 * vo.y;
    #pragma unroll
    for (int o = 16; o; o >>= 1) {
        pa += __shfl_xor_sync(0xffffffffu, pa, o);
        ps += __shfl_xor_sync(0xffffffffu, ps, o);
    }
    if (l == 0) { d_a[node] = pa; d_S[node] = ps + d_c2; }
}

// ---- layer2 scalar aggregation (CSR gather, unrolled) + pool bins --------
__global__ __launch_bounds__(256)
void k_scalar_pool(const int* __restrict__ batch) {
    __shared__ float sb[G];
    __shared__ float sc[G];
    int tid = threadIdx.x;
    if (tid < G) { sb[tid] = 0.f; sc[tid] = 0.f; }
    __syncthreads();
    int n = blockIdx.x * blockDim.x + tid;
    if (n < N_NODES) {
        int beg = d_off[n];
        int end = beg + d_deg[n];
        float s = 0.f;
        int j = beg;
        for (; j + 4 <= end; j += 4) {
            int2 e0 = d_ep[j],     e1 = d_ep[j + 1];
            int2 e2 = d_ep[j + 2], e3 = d_ep[j + 3];
            float v0 = d_a[e0.x], v1 = d_a[e1.x];
            float v2 = d_a[e2.x], v3 = d_a[e3.x];
            s = fmaf(__int_as_float(e0.y), v0, s);
            s = fmaf(__int_as_float(e1.y), v1, s);
            s = fmaf(__int_as_float(e2.y), v2, s);
            s = fmaf(__int_as_float(e3.y), v3, s);
        }
        for (; j < end; j++) {
            int2 e = d_ep[j];
            s = fmaf(__int_as_float(e.y), d_a[e.x], s);
        }
        float S = d_S[n] + s;
        int b = batch[n];
        atomicAdd(&sb[b], S);
        atomicAdd(&sc[b], 1.0f);
    }
    __syncthreads();
    if (tid < G && (sb[tid] != 0.f || sc[tid] != 0.f)) {
        atomicAdd(&d_gsum[tid], sb[tid]);
        atomicAdd(&d_gcnt[tid], sc[tid]);
    }
}

// ---------------- final ----------------------------------------------------
__global__ void k_final(const float* __restrict__ blin, float* __restrict__ out) {
    int g = threadIdx.x;
    if (g < G) out[g] = d_gsum[g] / fmaxf(d_gcnt[g], 1.0f) + blin[0];
}

// ---------------- launch ---------------------------------------------------
extern "C" void kernel_launch(void* const* d_in, const int* in_sizes, int n_in,
                              void* d_out, int out_size) {
    const float* x     = (const float*)d_in[0];
    const int*   ei    = (const int*)d_in[1];      // int32 (JAX x64 disabled)
    const float* ew    = (const float*)d_in[2];
    const int*   batch = (const int*)d_in[3];
    const float* w1rel = (const float*)d_in[4];
    const float* b1rel = (const float*)d_in[5];
    const float* w1rt  = (const float*)d_in[6];
    const float* w2rel = (const float*)d_in[7];
    const float* b2rel = (const float*)d_in[8];
    const float* w2rt  = (const float*)d_in[9];
    const float* wlin  = (const float*)d_in[10];
    const float* blin  = (const float*)d_in[11];
    float* out = (float*)d_out;

    cudaFuncSetAttribute(k_gemm, cudaFuncAttributeMaxDynamicSharedMemorySize,
                         SMEM_FLOATS * 4);

    k_init_zero<<<(N_NODES + 255) / 256, 256>>>(w2rel, w2rt, b2rel, wlin);
    k_gemm<<<GEMM_GRID, 256, SMEM_FLOATS * 4>>>(x, w1rel, w1rt, b1rel, ei);
    k_scanA<<<NSCAN, SCANB>>>();
    k_scanB<<<1, 32>>>();
    k_scanC<<<NSCAN, SCANB>>>();
    k_fill<<<(N_EDGES + 255) / 256, 256>>>(ei, ew);
    k_aggr<<<(N_NODES * 32 + 255) / 256, 256>>>();
    k_scalar_pool<<<(N_NODES + 255) / 256, 256>>>(batch);
    k_final<<<1, 128>>>(blin, out);
}